// round 6
// baseline (speedup 1.0000x reference)
#include <cuda_runtime.h>
#include <math.h>

#define BATCH 256
#define SLOPE 0.01f

// ---------------- static scratch ----------------
__device__ float    g_bufA[33554432];   // 134 MB
__device__ float    g_bufB[8388608];    // 33.5 MB
__device__ float    g_ze[BATCH * 256];
__device__ float    g_zq[BATCH * 256];
__device__ float    g_cnorm[8192];
__device__ double   g_sum[256];
__device__ double   g_sumsq[256];
__device__ float    g_mean[256];
__device__ float    g_rstd[256];
__device__ double   g_loss;
__device__ unsigned g_cnt;

// =================================================================
// init: zero stats + counter
// =================================================================
__global__ void init_zero()
{
    int i = threadIdx.x;
    g_sum[i] = 0.0; g_sumsq[i] = 0.0;
    if (i == 0) g_cnt = 0u;
}

// =================================================================
// Direct conv 3x3 s2 p1 + bias + LeakyReLU, optional fused input BN.
// Block: BB images x (OTH x OTW output tile) x OCB channels.
// Thread: 2x2 spatial x OCT channels.
// =================================================================
template<int CIN, int HIN, int WIN, int COUT, int OTH, int OTW,
         int BB, int OCB, int OCT, int CC>
__global__ void
__launch_bounds__((OTH / 2) * (OTW / 2) * BB * (OCB / OCT),
                  768 / ((OTH / 2) * (OTW / 2) * BB * (OCB / OCT)))
conv3s2(const float* __restrict__ in, const float* __restrict__ gw,
        const float* __restrict__ bias,
        const float* __restrict__ nmean, const float* __restrict__ nrstd,
        float* __restrict__ out)
{
    constexpr int HOUT = HIN / 2, WOUT = WIN / 2;
    constexpr int S    = (OTH / 2) * (OTW / 2);
    constexpr int G    = OCB / OCT;
    constexpr int BLK  = BB * S * G;
    constexpr int ITH  = 2 * OTH + 1, ITW = 2 * OTW + 1;
    constexpr int WROW = CC * 9 + 1;
    __shared__ float s_in[BB][CC][ITH][ITW];
    __shared__ float s_w[OCB][WROW];

    const int tid = threadIdx.x;
    const int sp  = tid % S;
    const int ib  = (tid / S) % BB;
    const int og  = tid / (S * BB);
    const int sy  = sp / (OTW / 2), sx = sp % (OTW / 2);

    constexpr int TX = WOUT / OTW, TY = HOUT / OTH;
    const int tile = blockIdx.x % (TX * TY);
    const int imgc = blockIdx.x / (TX * TY);
    const int tcx = tile % TX, tcy = tile / TX;
    const int ocBase = blockIdx.y * OCB;
    const int oy0 = tcy * OTH, ox0 = tcx * OTW;
    const int iy0 = oy0 * 2 - 1, ix0 = ox0 * 2 - 1;
    const bool donorm = (nmean != nullptr);

    float acc[2][2][OCT];
    #pragma unroll
    for (int dy = 0; dy < 2; dy++)
        #pragma unroll
        for (int dx = 0; dx < 2; dx++)
            #pragma unroll
            for (int j = 0; j < OCT; j++) acc[dy][dx][j] = 0.f;

    for (int c0 = 0; c0 < CIN; c0 += CC) {
        __syncthreads();
        for (int i = tid; i < BB * CC * ITH * ITW; i += BLK) {
            int lb = i / (CC * ITH * ITW);
            int r2 = i % (CC * ITH * ITW);
            int ic = r2 / (ITH * ITW);
            int r  = (r2 / ITW) % ITH;
            int cc = r2 % ITW;
            int gy = iy0 + r, gx = ix0 + cc;
            float v = 0.f;
            if (gy >= 0 && gy < HIN && gx >= 0 && gx < WIN) {
                v = in[((size_t)(imgc * BB + lb) * CIN + c0 + ic) * (HIN * WIN) + gy * WIN + gx];
                if (donorm) v = (v - nmean[c0 + ic]) * nrstd[c0 + ic];
            }
            s_in[lb][ic][r][cc] = v;
        }
        for (int i = tid; i < OCB * CC * 9; i += BLK) {
            int o = i / (CC * 9);
            int rem = i % (CC * 9);
            s_w[o][rem] = gw[((size_t)(ocBase + o) * CIN + c0) * 9 + rem];
        }
        __syncthreads();

        for (int ic = 0; ic < CC; ic++) {
            #pragma unroll
            for (int t = 0; t < 9; t++) {
                const int ky = t / 3, kx = t % 3;
                float w0[OCT];
                #pragma unroll
                for (int j = 0; j < OCT; j++) w0[j] = s_w[og * OCT + j][ic * 9 + t];
                #pragma unroll
                for (int dy = 0; dy < 2; dy++)
                    #pragma unroll
                    for (int dx = 0; dx < 2; dx++) {
                        float v = s_in[ib][ic][sy * 4 + dy * 2 + ky][sx * 4 + dx * 2 + kx];
                        #pragma unroll
                        for (int j = 0; j < OCT; j++)
                            acc[dy][dx][j] = fmaf(v, w0[j], acc[dy][dx][j]);
                    }
            }
        }
    }

    const int b = imgc * BB + ib;
    #pragma unroll
    for (int j = 0; j < OCT; j++) {
        int oc = ocBase + og * OCT + j;
        float bs = bias[oc];
        #pragma unroll
        for (int dy = 0; dy < 2; dy++)
            #pragma unroll
            for (int dx = 0; dx < 2; dx++) {
                int oy = oy0 + sy * 2 + dy, ox = ox0 + sx * 2 + dx;
                float r = acc[dy][dx][j] + bs;
                r = r >= 0.f ? r : SLOPE * r;
                out[((size_t)b * COUT + oc) * (HOUT * WOUT) + oy * WOUT + ox] = r;
            }
    }
}

// =================================================================
// convT 3x3 s2 p1 op1 + bias + LeakyReLU, optional fused input BN.
// Thread: 4x4 output tile (3x3 input regs) x OCT channels.
// =================================================================
template<int CIN, int HIN, int WIN, int COUT, int OTH, int OTW,
         int BB, int OCB, int OCT, int CC>
__global__ void convt3s2(const float* __restrict__ in, const float* __restrict__ gw,
                         const float* __restrict__ bias,
                         const float* __restrict__ nmean, const float* __restrict__ nrstd,
                         float* __restrict__ out)
{
    constexpr int HOUT = 2 * HIN, WOUT = 2 * WIN;
    constexpr int SP   = (OTH / 4) * (OTW / 4);
    constexpr int G    = OCB / OCT;
    constexpr int BLK  = BB * SP * G;
    constexpr int ITH  = OTH / 2 + 1, ITW = OTW / 2 + 1;
    constexpr int WROW = CC * 9 + 1;
    __shared__ float s_in[BB][CC][ITH][ITW];
    __shared__ float s_w[OCB][WROW];

    const int tid = threadIdx.x;
    const int sp  = tid % SP;
    const int ib  = (tid / SP) % BB;
    const int og  = tid / (SP * BB);
    const int ty  = sp / (OTW / 4), tx = sp % (OTW / 4);

    constexpr int TX = WOUT / OTW, TY = HOUT / OTH;
    const int tile = blockIdx.x % (TX * TY);
    const int imgc = blockIdx.x / (TX * TY);
    const int tcx = tile % TX, tcy = tile / TX;
    const int ocBase = blockIdx.y * OCB;
    const int oy0 = tcy * OTH, ox0 = tcx * OTW;
    const int iy0 = oy0 / 2, ix0 = ox0 / 2;
    const bool donorm = (nmean != nullptr);

    float acc[4][4][OCT];
    #pragma unroll
    for (int r = 0; r < 4; r++)
        #pragma unroll
        for (int c = 0; c < 4; c++)
            #pragma unroll
            for (int j = 0; j < OCT; j++) acc[r][c][j] = 0.f;

    for (int c0 = 0; c0 < CIN; c0 += CC) {
        __syncthreads();
        for (int i = tid; i < BB * CC * ITH * ITW; i += BLK) {
            int lb = i / (CC * ITH * ITW);
            int r2 = i % (CC * ITH * ITW);
            int ic = r2 / (ITH * ITW);
            int r  = (r2 / ITW) % ITH;
            int cc = r2 % ITW;
            int gy = iy0 + r, gx = ix0 + cc;
            float v = 0.f;
            if (gy < HIN && gx < WIN) {
                v = in[((size_t)(imgc * BB + lb) * CIN + c0 + ic) * (HIN * WIN) + gy * WIN + gx];
                if (donorm) v = (v - nmean[c0 + ic]) * nrstd[c0 + ic];
            }
            s_in[lb][ic][r][cc] = v;
        }
        for (int i = tid; i < CC * OCB * 9; i += BLK) {
            int ic = i / (OCB * 9);
            int r2 = i % (OCB * 9);
            int o = r2 / 9, t = r2 % 9;
            s_w[o][ic * 9 + t] = gw[((size_t)(c0 + ic) * COUT + ocBase) * 9 + r2];
        }
        __syncthreads();

        for (int ic = 0; ic < CC; ic++) {
            float v[3][3];
            #pragma unroll
            for (int a = 0; a < 3; a++)
                #pragma unroll
                for (int bb2 = 0; bb2 < 3; bb2++)
                    v[a][bb2] = s_in[ib][ic][2 * ty + a][2 * tx + bb2];
            #pragma unroll
            for (int j = 0; j < OCT; j++) {
                float wr[9];
                #pragma unroll
                for (int q = 0; q < 9; q++) wr[q] = s_w[og * OCT + j][ic * 9 + q];
                #pragma unroll
                for (int cy = 0; cy < 2; cy++)
                    #pragma unroll
                    for (int cx = 0; cx < 2; cx++) {
                        acc[2*cy  ][2*cx  ][j] = fmaf(wr[4], v[cy][cx],     acc[2*cy  ][2*cx  ][j]);
                        acc[2*cy  ][2*cx+1][j] = fmaf(wr[3], v[cy][cx+1],
                                                 fmaf(wr[5], v[cy][cx],     acc[2*cy  ][2*cx+1][j]));
                        acc[2*cy+1][2*cx  ][j] = fmaf(wr[1], v[cy+1][cx],
                                                 fmaf(wr[7], v[cy][cx],     acc[2*cy+1][2*cx  ][j]));
                        acc[2*cy+1][2*cx+1][j] = fmaf(wr[0], v[cy+1][cx+1],
                                                 fmaf(wr[2], v[cy+1][cx],
                                                 fmaf(wr[6], v[cy][cx+1],
                                                 fmaf(wr[8], v[cy][cx],     acc[2*cy+1][2*cx+1][j]))));
                    }
            }
        }
    }

    const int b = imgc * BB + ib;
    #pragma unroll
    for (int j = 0; j < OCT; j++) {
        int oc = ocBase + og * OCT + j;
        float bs = bias[oc];
        #pragma unroll
        for (int r = 0; r < 4; r++)
            #pragma unroll
            for (int c = 0; c < 4; c++) {
                int oy = oy0 + 4 * ty + r, ox = ox0 + 4 * tx + c;
                float rv = acc[r][c][j] + bs;
                rv = rv >= 0.f ? rv : SLOPE * rv;
                out[((size_t)b * COUT + oc) * (HOUT * WOUT) + oy * WOUT + ox] = rv;
            }
    }
}

// =================================================================
// Final convT (s1 p1) == conv3x3 with flipped weights, + tanh head.
// 32x32 tile / block, 128 threads, each thread 4x2 spatial x 3 oc.
// CC=8 input-channel chunks.
// =================================================================
__global__ void __launch_bounds__(128, 5)
convt4_s1_tanh(const float* __restrict__ in, const float* __restrict__ gw,
               const float* __restrict__ bias,
               const float* __restrict__ nmean, const float* __restrict__ nrstd,
               float* __restrict__ out)
{
    __shared__ float s_in[8][34][34];
    __shared__ float s_w[8][3][9];
    const int tid = threadIdx.x;             // 128
    const int py = tid / 16, px = tid % 16;  // 8 x 16 threads; each 4 rows x 2 cols
    const int bx = blockIdx.x;
    const int tcx = bx % 2, tcy = (bx / 2) % 2, b = bx / 4;
    const int oy0 = tcy * 32, ox0 = tcx * 32;

    float acc[4][2][3];
    #pragma unroll
    for (int r = 0; r < 4; r++)
        #pragma unroll
        for (int c = 0; c < 2; c++)
            #pragma unroll
            for (int o = 0; o < 3; o++) acc[r][c][o] = 0.f;

    for (int c0 = 0; c0 < 32; c0 += 8) {
        __syncthreads();
        for (int i = tid; i < 8 * 34 * 34; i += 128) {
            int ic = i / 1156, r = (i / 34) % 34, c = i % 34;
            int gy = oy0 - 1 + r, gx = ox0 - 1 + c;
            float v = 0.f;
            if (gy >= 0 && gy < 64 && gx >= 0 && gx < 64)
                v = (in[((size_t)b * 32 + c0 + ic) * 4096 + gy * 64 + gx]
                     - nmean[c0 + ic]) * nrstd[c0 + ic];
            s_in[ic][r][c] = v;
        }
        for (int i = tid; i < 8 * 27; i += 128) {
            int ic = i / 27, rem = i % 27;
            s_w[ic][rem / 9][rem % 9] = gw[(c0 + ic) * 27 + rem];
        }
        __syncthreads();

        for (int ic = 0; ic < 8; ic++) {
            float v[6][4];
            #pragma unroll
            for (int r = 0; r < 6; r++)
                #pragma unroll
                for (int c = 0; c < 4; c++)
                    v[r][c] = s_in[ic][py * 4 + r][px * 2 + c];
            float wf[3][9];
            #pragma unroll
            for (int o = 0; o < 3; o++)
                #pragma unroll
                for (int t = 0; t < 9; t++)
                    wf[o][t] = s_w[ic][o][8 - t];
            #pragma unroll
            for (int t = 0; t < 9; t++) {
                const int ky = t / 3, kx = t % 3;
                #pragma unroll
                for (int r = 0; r < 4; r++)
                    #pragma unroll
                    for (int c = 0; c < 2; c++) {
                        float vv = v[r + ky][c + kx];
                        #pragma unroll
                        for (int o = 0; o < 3; o++)
                            acc[r][c][o] = fmaf(vv, wf[o][t], acc[r][c][o]);
                    }
            }
        }
    }

    #pragma unroll
    for (int o = 0; o < 3; o++) {
        float bs = bias[o];
        #pragma unroll
        for (int r = 0; r < 4; r++)
            #pragma unroll
            for (int c = 0; c < 2; c++) {
                int oy = oy0 + py * 4 + r, ox = ox0 + px * 2 + c;
                out[((size_t)b * 3 + o) * 4096 + oy * 64 + ox] =
                    0.5f + 0.5f * tanhf(acc[r][c][o] + bs);
            }
    }
}

// =================================================================
// BN stats: reduce + last-block finalize (mean/rstd) + self-zero.
// grid (C, NS); HW = 1<<hwshift.
// =================================================================
__global__ void bn_stats(const float* __restrict__ x, int C, int hwshift,
                         float invn, int nblocks)
{
    const int c = blockIdx.x;
    const int split = blockIdx.y, NS = gridDim.y;
    const int HW = 1 << hwshift;
    const int per = BATCH / NS;
    float s = 0.f, s2 = 0.f;
    for (int i = threadIdx.x; i < per * HW; i += blockDim.x) {
        int b = split + (i >> hwshift) * NS;
        int pos = i & (HW - 1);
        float v = x[((size_t)b * C + c) * HW + pos];
        s += v; s2 = fmaf(v, v, s2);
    }
    __shared__ float sh[256], sh2[256];
    __shared__ bool s_last;
    sh[threadIdx.x] = s; sh2[threadIdx.x] = s2;
    __syncthreads();
    for (int st = 128; st > 0; st >>= 1) {
        if (threadIdx.x < st) {
            sh[threadIdx.x]  += sh[threadIdx.x + st];
            sh2[threadIdx.x] += sh2[threadIdx.x + st];
        }
        __syncthreads();
    }
    if (threadIdx.x == 0) {
        atomicAdd(&g_sum[c],   (double)sh[0]);
        atomicAdd(&g_sumsq[c], (double)sh2[0]);
        __threadfence();
        unsigned p = atomicAdd(&g_cnt, 1u);
        s_last = (p == (unsigned)(nblocks - 1));
    }
    __syncthreads();
    if (s_last) {
        int t = threadIdx.x;
        if (t < C) {
            double mu  = ((volatile double*)g_sum)[t]   * (double)invn;
            double var = ((volatile double*)g_sumsq)[t] * (double)invn - mu * mu;
            g_mean[t] = (float)mu;
            g_rstd[t] = (float)rsqrt(var + 1e-5);
            g_sum[t] = 0.0; g_sumsq[t] = 0.0;
        }
        __syncthreads();
        if (t == 0) g_cnt = 0u;
    }
}

// =================================================================
// 64x64 register-blocked GEMM (full K), + bias/act.
// =================================================================
__global__ void gemm64(const float* __restrict__ A, const float* __restrict__ Wt,
                       const float* __restrict__ bias, float* __restrict__ C,
                       int M, int N, int K, int ldc, int act)
{
    __shared__ float sA[64][17];
    __shared__ float sB[64][17];
    const int tid = threadIdx.x;
    const int tx = tid % 16, ty = tid / 16;
    const int m0 = blockIdx.y * 64, n0 = blockIdx.x * 64;

    float acc[4][4];
    #pragma unroll
    for (int i = 0; i < 4; i++)
        #pragma unroll
        for (int j = 0; j < 4; j++) acc[i][j] = 0.f;

    for (int k0 = 0; k0 < K; k0 += 16) {
        __syncthreads();
        #pragma unroll
        for (int l = 0; l < 4; l++) {
            int i = tid + l * 256;
            int r = i / 16, c = i % 16;
            sA[r][c] = A[(size_t)(m0 + r) * K + k0 + c];
            sB[r][c] = Wt[(size_t)(n0 + r) * K + k0 + c];
        }
        __syncthreads();
        #pragma unroll
        for (int kk = 0; kk < 16; kk++) {
            float a[4], bb[4];
            #pragma unroll
            for (int i = 0; i < 4; i++) a[i] = sA[ty * 4 + i][kk];
            #pragma unroll
            for (int j = 0; j < 4; j++) bb[j] = sB[tx * 4 + j][kk];
            #pragma unroll
            for (int i = 0; i < 4; i++)
                #pragma unroll
                for (int j = 0; j < 4; j++)
                    acc[i][j] = fmaf(a[i], bb[j], acc[i][j]);
        }
    }
    #pragma unroll
    for (int i = 0; i < 4; i++) {
        int m = m0 + ty * 4 + i;
        #pragma unroll
        for (int j = 0; j < 4; j++) {
            int n = n0 + tx * 4 + j;
            float r = acc[i][j];
            if (bias) r += bias[n];
            if (act == 1) r = fmaxf(r, 0.f);
            C[(size_t)m * ldc + n] = r;
        }
    }
}

// =================================================================
// FC heads, deterministic split-K: partials to `part`, fused BN on A.
// grid (4 nblk, 4 mblk, Z). N total 256: n<128 -> mu head, else cov head.
// =================================================================
__global__ void gemm_heads_splitk(const float* __restrict__ A,
                                  const float* __restrict__ Wmu,
                                  const float* __restrict__ Wcov,
                                  float* __restrict__ part, int KS)
{
    __shared__ float sA[64][17];
    __shared__ float sB[64][17];
    const int tid = threadIdx.x;
    const int tx = tid % 16, ty = tid / 16;
    const int m0 = blockIdx.y * 64, n0 = blockIdx.x * 64;
    const float* Wt = (n0 < 128) ? (Wmu + (size_t)n0 * 4096) : (Wcov + (size_t)(n0 - 128) * 4096);
    const int kbase = blockIdx.z * KS;

    float acc[4][4];
    #pragma unroll
    for (int i = 0; i < 4; i++)
        #pragma unroll
        for (int j = 0; j < 4; j++) acc[i][j] = 0.f;

    for (int k0 = kbase; k0 < kbase + KS; k0 += 16) {
        __syncthreads();
        #pragma unroll
        for (int l = 0; l < 4; l++) {
            int i = tid + l * 256;
            int r = i / 16, c = i % 16;
            int k = k0 + c;
            int ch = k >> 4;
            sA[r][c] = (A[(size_t)(m0 + r) * 4096 + k] - g_mean[ch]) * g_rstd[ch];
            sB[r][c] = Wt[(size_t)r * 4096 + k];
        }
        __syncthreads();
        #pragma unroll
        for (int kk = 0; kk < 16; kk++) {
            float a[4], bb[4];
            #pragma unroll
            for (int i = 0; i < 4; i++) a[i] = sA[ty * 4 + i][kk];
            #pragma unroll
            for (int j = 0; j < 4; j++) bb[j] = sB[tx * 4 + j][kk];
            #pragma unroll
            for (int i = 0; i < 4; i++)
                #pragma unroll
                for (int j = 0; j < 4; j++)
                    acc[i][j] = fmaf(a[i], bb[j], acc[i][j]);
        }
    }
    #pragma unroll
    for (int i = 0; i < 4; i++) {
        int m = m0 + ty * 4 + i;
        #pragma unroll
        for (int j = 0; j < 4; j++) {
            int n = n0 + tx * 4 + j;
            part[((size_t)blockIdx.z * 256 + m) * 256 + n] = acc[i][j];
        }
    }
}

__global__ void head_combine(const float* __restrict__ part,
                             const float* __restrict__ bmu,
                             const float* __restrict__ bcov, int Z)
{
    int m = blockIdx.x, n = threadIdx.x;
    float s = 0.f;
    for (int z = 0; z < Z; z++) s += part[((size_t)z * 256 + m) * 256 + n];
    if (n < 128) s += bmu[n];
    else { s += bcov[n - 128]; s = fmaxf(s, 0.f); }
    g_ze[m * 256 + n] = s;
}

// ---------------- codebook norms + zero loss ----------------
__global__ void cnorm_k(const float* __restrict__ cb)
{
    int gwarp = (blockIdx.x * blockDim.x + threadIdx.x) >> 5;
    int lane = threadIdx.x & 31;
    if (gwarp < 8192) {
        const float* p = cb + (size_t)gwarp * 256;
        float s = 0.f;
        for (int d = lane; d < 256; d += 32) { float v = p[d]; s = fmaf(v, v, s); }
        #pragma unroll
        for (int o = 16; o; o >>= 1) s += __shfl_xor_sync(0xffffffffu, s, o);
        if (lane == 0) g_cnorm[gwarp] = s;
    }
    if (blockIdx.x == 0 && threadIdx.x == 0) g_loss = 0.0;
}

// ---------------- VQ argmin + gather + loss ----------------
__global__ void vq_argmin(const float* __restrict__ S, const float* __restrict__ cb)
{
    int b = blockIdx.x;
    int tid = threadIdx.x;
    float best = INFINITY; int bi = 0x7fffffff;
    const float* Sb = S + (size_t)b * 8192;
    for (int k = tid; k < 8192; k += 256) {
        float d = g_cnorm[k] - 2.f * Sb[k];
        if (d < best || (d == best && k < bi)) { best = d; bi = k; }
    }
    __shared__ float sv[256];
    __shared__ int   si[256];
    sv[tid] = best; si[tid] = bi;
    __syncthreads();
    for (int st = 128; st > 0; st >>= 1) {
        if (tid < st) {
            if (sv[tid + st] < sv[tid] ||
               (sv[tid + st] == sv[tid] && si[tid + st] < si[tid])) {
                sv[tid] = sv[tid + st]; si[tid] = si[tid + st];
            }
        }
        __syncthreads();
    }
    int idx = si[0];
    float cv = cb[(size_t)idx * 256 + tid];
    float diff = g_ze[b * 256 + tid] - cv;
    g_zq[b * 256 + tid] = cv;
    __shared__ double sl[256];
    sl[tid] = (double)diff * diff;
    __syncthreads();
    for (int st = 128; st > 0; st >>= 1) {
        if (tid < st) sl[tid] += sl[tid + st];
        __syncthreads();
    }
    if (tid == 0) atomicAdd(&g_loss, sl[0]);
}

__global__ void write_loss(float* out, long long pos)
{
    out[pos] = (float)(2.0 * g_loss);
}

// ---------------- host orchestration ----------------
extern "C" void kernel_launch(void* const* d_in, const int* in_sizes, int n_in,
                              void* d_out, int out_size)
{
    const float* x     = (const float*)d_in[0];
    const float* ew1   = (const float*)d_in[1];
    const float* eb1   = (const float*)d_in[2];
    const float* ew2   = (const float*)d_in[3];
    const float* eb2   = (const float*)d_in[4];
    const float* ew3   = (const float*)d_in[5];
    const float* eb3   = (const float*)d_in[6];
    const float* ew4   = (const float*)d_in[7];
    const float* eb4   = (const float*)d_in[8];
    const float* ewmu  = (const float*)d_in[9];
    const float* ebmu  = (const float*)d_in[10];
    const float* ewcov = (const float*)d_in[11];
    const float* ebcov = (const float*)d_in[12];
    const float* cb    = (const float*)d_in[13];
    const float* dwfc  = (const float*)d_in[14];
    const float* dbfc  = (const float*)d_in[15];
    const float* dwt1  = (const float*)d_in[16];
    const float* dbt1  = (const float*)d_in[17];
    const float* dwt2  = (const float*)d_in[18];
    const float* dbt2  = (const float*)d_in[19];
    const float* dwt3  = (const float*)d_in[20];
    const float* dbt3  = (const float*)d_in[21];
    const float* dwt31 = (const float*)d_in[22];
    const float* dbt31 = (const float*)d_in[23];
    const float* dwt4  = (const float*)d_in[24];
    const float* dbt4  = (const float*)d_in[25];
    float* out = (float*)d_out;

    float *A, *Bf, *ze, *zq, *gm, *gr;
    cudaGetSymbolAddress((void**)&A,  g_bufA);
    cudaGetSymbolAddress((void**)&Bf, g_bufB);
    cudaGetSymbolAddress((void**)&ze, g_ze);
    cudaGetSymbolAddress((void**)&zq, g_zq);
    cudaGetSymbolAddress((void**)&gm, g_mean);
    cudaGetSymbolAddress((void**)&gr, g_rstd);

    init_zero<<<1, 256>>>();

    // ---- Encoder ----
    // conv1: x [256,3,64,64] -> Bf [256,32,32,32]
    conv3s2<3, 64, 64, 32, 16, 16, 1, 32, 8, 3>
        <<<dim3(1024, 1), 256>>>(x, ew1, eb1, nullptr, nullptr, Bf);
    bn_stats<<<dim3(32, 32), 256>>>(Bf, 32, 10, 1.f / (256.f * 1024.f), 32 * 32);

    // conv2: Bf -> A [256,64,16,16]
    conv3s2<32, 32, 32, 64, 16, 16, 1, 32, 8, 4>
        <<<dim3(256, 2), 256>>>(Bf, ew2, eb2, gm, gr, A);
    bn_stats<<<dim3(64, 16), 256>>>(A, 64, 8, 1.f / (256.f * 256.f), 64 * 16);

    // conv3: A -> Bf [256,128,8,8]
    conv3s2<64, 16, 16, 128, 8, 8, 1, 32, 8, 4>
        <<<dim3(256, 4), 64>>>(A, ew3, eb3, gm, gr, Bf);
    bn_stats<<<dim3(128, 8), 256>>>(Bf, 128, 6, 1.f / (256.f * 64.f), 128 * 8);

    // conv4: Bf -> A [256,256,4,4]
    conv3s2<128, 8, 8, 256, 4, 4, 4, 32, 8, 8>
        <<<dim3(64, 8), 64>>>(Bf, ew4, eb4, gm, gr, A);
    bn_stats<<<dim3(256, 4), 256>>>(A, 256, 4, 1.f / (256.f * 16.f), 256 * 4);

    // ---- FC heads (split-K, BN4 fused), partials in Bf ----
    gemm_heads_splitk<<<dim3(4, 4, 8), 256>>>(A, ewmu, ewcov, Bf, 512);
    head_combine<<<256, 256>>>(Bf, ebmu, ebcov, 8);

    // ---- VQ ----
    cnorm_k<<<1024, 256>>>(cb);
    gemm64<<<dim3(128, 4), 256>>>(ze, cb, nullptr, Bf, 256, 8192, 256, 8192, 0);
    vq_argmin<<<BATCH, 256>>>(Bf, cb);

    // ---- Decoder FC ----
    gemm64<<<dim3(64, 4), 256>>>(zq, dwfc, dbfc, A, 256, 4096, 256, 4096, 0);

    // ---- Decoder ----
    convt3s2<256, 4, 4, 128, 8, 8, 2, 64, 4, 16>
        <<<dim3(128, 2), 128>>>(A, dwt1, dbt1, nullptr, nullptr, Bf);
    bn_stats<<<dim3(128, 8), 256>>>(Bf, 128, 6, 1.f / (256.f * 64.f), 128 * 8);

    convt3s2<128, 8, 8, 64, 16, 16, 1, 64, 4, 16>
        <<<dim3(256, 1), 256>>>(Bf, dwt2, dbt2, gm, gr, A);
    bn_stats<<<dim3(64, 16), 256>>>(A, 64, 8, 1.f / (256.f * 256.f), 64 * 16);

    convt3s2<64, 16, 16, 32, 32, 32, 1, 32, 4, 16>
        <<<dim3(256, 1), 512>>>(A, dwt3, dbt3, gm, gr, Bf);
    bn_stats<<<dim3(32, 32), 256>>>(Bf, 32, 10, 1.f / (256.f * 1024.f), 32 * 32);

    convt3s2<32, 32, 32, 32, 32, 32, 1, 32, 4, 16>
        <<<dim3(1024, 1), 512>>>(Bf, dwt31, dbt31, gm, gr, A);
    bn_stats<<<dim3(32, 32), 256>>>(A, 32, 12, 1.f / (256.f * 4096.f), 32 * 32);

    // T4 (s1) + tanh: A -> out [256,3,64,64]
    convt4_s1_tanh<<<dim3(1024, 1), 128>>>(A, dwt4, dbt4, gm, gr, out);

    // ---- scalar vq_loss ----
    write_loss<<<1, 1>>>(out, (long long)out_size - 1);
}

// round 7
// speedup vs baseline: 1.1374x; 1.1374x over previous
#include <cuda_runtime.h>
#include <math.h>

#define BATCH 256
#define SLOPE 0.01f

// ---------------- static scratch ----------------
__device__ float    g_bufA[33554432];   // 134 MB
__device__ float    g_bufB[8388608];    // 33.5 MB
__device__ float    g_ze[BATCH * 256];
__device__ float    g_zq[BATCH * 256];
__device__ float    g_cnorm[8192];
__device__ double   g_sum[256];
__device__ double   g_sumsq[256];
__device__ float    g_mean[256];
__device__ float    g_rstd[256];
__device__ double   g_loss;

// =================================================================
// init: zero stats
// =================================================================
__global__ void init_zero()
{
    int i = threadIdx.x;
    g_sum[i] = 0.0; g_sumsq[i] = 0.0;
}

// =================================================================
// bn_finalize: mean/rstd from accumulated sums, then re-zero sums.
// =================================================================
__global__ void bn_finalize(int C, float invn)
{
    int c = threadIdx.x;
    if (c < C) {
        double mu  = g_sum[c] * (double)invn;
        double var = g_sumsq[c] * (double)invn - mu * mu;
        g_mean[c] = (float)mu;
        g_rstd[c] = (float)rsqrt(var + 1e-5);
        g_sum[c] = 0.0; g_sumsq[c] = 0.0;
    }
}

// =================================================================
// Direct conv 3x3 s2 p1 + bias + LeakyReLU, optional fused input BN.
// Fused OUTPUT BN-stat accumulation in epilogue.
// Thread: 2x2 spatial x OCT channels.
// =================================================================
template<int CIN, int HIN, int WIN, int COUT, int OTH, int OTW,
         int BB, int OCB, int OCT, int CC>
__global__ void conv3s2(const float* __restrict__ in, const float* __restrict__ gw,
                        const float* __restrict__ bias,
                        const float* __restrict__ nmean, const float* __restrict__ nrstd,
                        float* __restrict__ out)
{
    constexpr int HOUT = HIN / 2, WOUT = WIN / 2;
    constexpr int S    = (OTH / 2) * (OTW / 2);
    constexpr int G    = OCB / OCT;
    constexpr int BLK  = BB * S * G;
    constexpr int ITH  = 2 * OTH + 1, ITW = 2 * OTW + 1;
    constexpr int WROW = CC * 9 + 1;
    constexpr int TPC  = BB * S;                    // threads per channel group
    constexpr int SEG  = (TPC >= 32) ? 32 : TPC;    // shfl segment (power of 2)
    __shared__ float s_in[BB][CC][ITH][ITW];
    __shared__ float s_w[OCB][WROW];
    __shared__ float sh_bns[OCB], sh_bns2[OCB];

    const int tid = threadIdx.x;
    const int sp  = tid % S;
    const int ib  = (tid / S) % BB;
    const int og  = tid / (S * BB);
    const int sy  = sp / (OTW / 2), sx = sp % (OTW / 2);

    constexpr int TX = WOUT / OTW, TY = HOUT / OTH;
    const int tile = blockIdx.x % (TX * TY);
    const int imgc = blockIdx.x / (TX * TY);
    const int tcx = tile % TX, tcy = tile / TX;
    const int ocBase = blockIdx.y * OCB;
    const int oy0 = tcy * OTH, ox0 = tcx * OTW;
    const int iy0 = oy0 * 2 - 1, ix0 = ox0 * 2 - 1;
    const bool donorm = (nmean != nullptr);

    for (int i = tid; i < OCB; i += BLK) { sh_bns[i] = 0.f; sh_bns2[i] = 0.f; }

    float acc[2][2][OCT];
    #pragma unroll
    for (int dy = 0; dy < 2; dy++)
        #pragma unroll
        for (int dx = 0; dx < 2; dx++)
            #pragma unroll
            for (int j = 0; j < OCT; j++) acc[dy][dx][j] = 0.f;

    for (int c0 = 0; c0 < CIN; c0 += CC) {
        __syncthreads();
        for (int i = tid; i < BB * CC * ITH * ITW; i += BLK) {
            int lb = i / (CC * ITH * ITW);
            int r2 = i % (CC * ITH * ITW);
            int ic = r2 / (ITH * ITW);
            int r  = (r2 / ITW) % ITH;
            int cc = r2 % ITW;
            int gy = iy0 + r, gx = ix0 + cc;
            float v = 0.f;
            if (gy >= 0 && gy < HIN && gx >= 0 && gx < WIN) {
                v = in[((size_t)(imgc * BB + lb) * CIN + c0 + ic) * (HIN * WIN) + gy * WIN + gx];
                if (donorm) v = (v - nmean[c0 + ic]) * nrstd[c0 + ic];
            }
            s_in[lb][ic][r][cc] = v;
        }
        for (int i = tid; i < OCB * CC * 9; i += BLK) {
            int o = i / (CC * 9);
            int rem = i % (CC * 9);
            s_w[o][rem] = gw[((size_t)(ocBase + o) * CIN + c0) * 9 + rem];
        }
        __syncthreads();

        for (int ic = 0; ic < CC; ic++) {
            #pragma unroll
            for (int t = 0; t < 9; t++) {
                const int ky = t / 3, kx = t % 3;
                float w0[OCT];
                #pragma unroll
                for (int j = 0; j < OCT; j++) w0[j] = s_w[og * OCT + j][ic * 9 + t];
                #pragma unroll
                for (int dy = 0; dy < 2; dy++)
                    #pragma unroll
                    for (int dx = 0; dx < 2; dx++) {
                        float v = s_in[ib][ic][sy * 4 + dy * 2 + ky][sx * 4 + dx * 2 + kx];
                        #pragma unroll
                        for (int j = 0; j < OCT; j++)
                            acc[dy][dx][j] = fmaf(v, w0[j], acc[dy][dx][j]);
                    }
            }
        }
    }

    const int b = imgc * BB + ib;
    #pragma unroll
    for (int j = 0; j < OCT; j++) {
        int oc = ocBase + og * OCT + j;
        float bs = bias[oc];
        float sj = 0.f, s2j = 0.f;
        #pragma unroll
        for (int dy = 0; dy < 2; dy++)
            #pragma unroll
            for (int dx = 0; dx < 2; dx++) {
                int oy = oy0 + sy * 2 + dy, ox = ox0 + sx * 2 + dx;
                float r = acc[dy][dx][j] + bs;
                r = r >= 0.f ? r : SLOPE * r;
                out[((size_t)b * COUT + oc) * (HOUT * WOUT) + oy * WOUT + ox] = r;
                sj += r; s2j = fmaf(r, r, s2j);
            }
        #pragma unroll
        for (int o = SEG / 2; o; o >>= 1) {
            sj  += __shfl_down_sync(0xffffffffu, sj,  o, SEG);
            s2j += __shfl_down_sync(0xffffffffu, s2j, o, SEG);
        }
        if ((tid & (SEG - 1)) == 0) {
            atomicAdd(&sh_bns[og * OCT + j],  sj);
            atomicAdd(&sh_bns2[og * OCT + j], s2j);
        }
    }
    __syncthreads();
    for (int i = tid; i < OCB; i += BLK) {
        atomicAdd(&g_sum[ocBase + i],   (double)sh_bns[i]);
        atomicAdd(&g_sumsq[ocBase + i], (double)sh_bns2[i]);
    }
}

// =================================================================
// convT 3x3 s2 p1 op1 + bias + LeakyReLU, optional fused input BN.
// Fused OUTPUT BN-stat accumulation in epilogue.
// Thread: 4x4 output tile (3x3 input regs) x OCT channels.
// =================================================================
template<int CIN, int HIN, int WIN, int COUT, int OTH, int OTW,
         int BB, int OCB, int OCT, int CC>
__global__ void convt3s2(const float* __restrict__ in, const float* __restrict__ gw,
                         const float* __restrict__ bias,
                         const float* __restrict__ nmean, const float* __restrict__ nrstd,
                         float* __restrict__ out)
{
    constexpr int HOUT = 2 * HIN, WOUT = 2 * WIN;
    constexpr int SP   = (OTH / 4) * (OTW / 4);
    constexpr int G    = OCB / OCT;
    constexpr int BLK  = BB * SP * G;
    constexpr int ITH  = OTH / 2 + 1, ITW = OTW / 2 + 1;
    constexpr int WROW = CC * 9 + 1;
    constexpr int TPC  = BB * SP;
    constexpr int SEG  = (TPC >= 32) ? 32 : TPC;
    __shared__ float s_in[BB][CC][ITH][ITW];
    __shared__ float s_w[OCB][WROW];
    __shared__ float sh_bns[OCB], sh_bns2[OCB];

    const int tid = threadIdx.x;
    const int sp  = tid % SP;
    const int ib  = (tid / SP) % BB;
    const int og  = tid / (SP * BB);
    const int ty  = sp / (OTW / 4), tx = sp % (OTW / 4);

    constexpr int TX = WOUT / OTW, TY = HOUT / OTH;
    const int tile = blockIdx.x % (TX * TY);
    const int imgc = blockIdx.x / (TX * TY);
    const int tcx = tile % TX, tcy = tile / TX;
    const int ocBase = blockIdx.y * OCB;
    const int oy0 = tcy * OTH, ox0 = tcx * OTW;
    const int iy0 = oy0 / 2, ix0 = ox0 / 2;
    const bool donorm = (nmean != nullptr);

    for (int i = tid; i < OCB; i += BLK) { sh_bns[i] = 0.f; sh_bns2[i] = 0.f; }

    float acc[4][4][OCT];
    #pragma unroll
    for (int r = 0; r < 4; r++)
        #pragma unroll
        for (int c = 0; c < 4; c++)
            #pragma unroll
            for (int j = 0; j < OCT; j++) acc[r][c][j] = 0.f;

    for (int c0 = 0; c0 < CIN; c0 += CC) {
        __syncthreads();
        for (int i = tid; i < BB * CC * ITH * ITW; i += BLK) {
            int lb = i / (CC * ITH * ITW);
            int r2 = i % (CC * ITH * ITW);
            int ic = r2 / (ITH * ITW);
            int r  = (r2 / ITW) % ITH;
            int cc = r2 % ITW;
            int gy = iy0 + r, gx = ix0 + cc;
            float v = 0.f;
            if (gy < HIN && gx < WIN) {
                v = in[((size_t)(imgc * BB + lb) * CIN + c0 + ic) * (HIN * WIN) + gy * WIN + gx];
                if (donorm) v = (v - nmean[c0 + ic]) * nrstd[c0 + ic];
            }
            s_in[lb][ic][r][cc] = v;
        }
        for (int i = tid; i < CC * OCB * 9; i += BLK) {
            int ic = i / (OCB * 9);
            int r2 = i % (OCB * 9);
            int o = r2 / 9, t = r2 % 9;
            s_w[o][ic * 9 + t] = gw[((size_t)(c0 + ic) * COUT + ocBase) * 9 + r2];
        }
        __syncthreads();

        for (int ic = 0; ic < CC; ic++) {
            float v[3][3];
            #pragma unroll
            for (int a = 0; a < 3; a++)
                #pragma unroll
                for (int bb2 = 0; bb2 < 3; bb2++)
                    v[a][bb2] = s_in[ib][ic][2 * ty + a][2 * tx + bb2];
            #pragma unroll
            for (int j = 0; j < OCT; j++) {
                float wr[9];
                #pragma unroll
                for (int q = 0; q < 9; q++) wr[q] = s_w[og * OCT + j][ic * 9 + q];
                #pragma unroll
                for (int cy = 0; cy < 2; cy++)
                    #pragma unroll
                    for (int cx = 0; cx < 2; cx++) {
                        acc[2*cy  ][2*cx  ][j] = fmaf(wr[4], v[cy][cx],     acc[2*cy  ][2*cx  ][j]);
                        acc[2*cy  ][2*cx+1][j] = fmaf(wr[3], v[cy][cx+1],
                                                 fmaf(wr[5], v[cy][cx],     acc[2*cy  ][2*cx+1][j]));
                        acc[2*cy+1][2*cx  ][j] = fmaf(wr[1], v[cy+1][cx],
                                                 fmaf(wr[7], v[cy][cx],     acc[2*cy+1][2*cx  ][j]));
                        acc[2*cy+1][2*cx+1][j] = fmaf(wr[0], v[cy+1][cx+1],
                                                 fmaf(wr[2], v[cy+1][cx],
                                                 fmaf(wr[6], v[cy][cx+1],
                                                 fmaf(wr[8], v[cy][cx],     acc[2*cy+1][2*cx+1][j]))));
                    }
            }
        }
    }

    const int b = imgc * BB + ib;
    #pragma unroll
    for (int j = 0; j < OCT; j++) {
        int oc = ocBase + og * OCT + j;
        float bs = bias[oc];
        float sj = 0.f, s2j = 0.f;
        #pragma unroll
        for (int r = 0; r < 4; r++)
            #pragma unroll
            for (int c = 0; c < 4; c++) {
                int oy = oy0 + 4 * ty + r, ox = ox0 + 4 * tx + c;
                float rv = acc[r][c][j] + bs;
                rv = rv >= 0.f ? rv : SLOPE * rv;
                out[((size_t)b * COUT + oc) * (HOUT * WOUT) + oy * WOUT + ox] = rv;
                sj += rv; s2j = fmaf(rv, rv, s2j);
            }
        #pragma unroll
        for (int o = SEG / 2; o; o >>= 1) {
            sj  += __shfl_down_sync(0xffffffffu, sj,  o, SEG);
            s2j += __shfl_down_sync(0xffffffffu, s2j, o, SEG);
        }
        if ((tid & (SEG - 1)) == 0) {
            atomicAdd(&sh_bns[og * OCT + j],  sj);
            atomicAdd(&sh_bns2[og * OCT + j], s2j);
        }
    }
    __syncthreads();
    for (int i = tid; i < OCB; i += BLK) {
        atomicAdd(&g_sum[ocBase + i],   (double)sh_bns[i]);
        atomicAdd(&g_sumsq[ocBase + i], (double)sh_bns2[i]);
    }
}

// =================================================================
// Final convT (s1 p1) == conv3x3 with flipped weights, + tanh head.
// 32x32 tile / block, 128 threads, each thread 4x2 spatial x 3 oc.
// =================================================================
__global__ void __launch_bounds__(128, 5)
convt4_s1_tanh(const float* __restrict__ in, const float* __restrict__ gw,
               const float* __restrict__ bias,
               const float* __restrict__ nmean, const float* __restrict__ nrstd,
               float* __restrict__ out)
{
    __shared__ float s_in[8][34][34];
    __shared__ float s_w[8][3][9];
    const int tid = threadIdx.x;             // 128
    const int py = tid / 16, px = tid % 16;  // 8 x 16 threads; each 4 rows x 2 cols
    const int bx = blockIdx.x;
    const int tcx = bx % 2, tcy = (bx / 2) % 2, b = bx / 4;
    const int oy0 = tcy * 32, ox0 = tcx * 32;

    float acc[4][2][3];
    #pragma unroll
    for (int r = 0; r < 4; r++)
        #pragma unroll
        for (int c = 0; c < 2; c++)
            #pragma unroll
            for (int o = 0; o < 3; o++) acc[r][c][o] = 0.f;

    for (int c0 = 0; c0 < 32; c0 += 8) {
        __syncthreads();
        for (int i = tid; i < 8 * 34 * 34; i += 128) {
            int ic = i / 1156, r = (i / 34) % 34, c = i % 34;
            int gy = oy0 - 1 + r, gx = ox0 - 1 + c;
            float v = 0.f;
            if (gy >= 0 && gy < 64 && gx >= 0 && gx < 64)
                v = (in[((size_t)b * 32 + c0 + ic) * 4096 + gy * 64 + gx]
                     - nmean[c0 + ic]) * nrstd[c0 + ic];
            s_in[ic][r][c] = v;
        }
        for (int i = tid; i < 8 * 27; i += 128) {
            int ic = i / 27, rem = i % 27;
            s_w[ic][rem / 9][rem % 9] = gw[(c0 + ic) * 27 + rem];
        }
        __syncthreads();

        for (int ic = 0; ic < 8; ic++) {
            float v[6][4];
            #pragma unroll
            for (int r = 0; r < 6; r++)
                #pragma unroll
                for (int c = 0; c < 4; c++)
                    v[r][c] = s_in[ic][py * 4 + r][px * 2 + c];
            float wf[3][9];
            #pragma unroll
            for (int o = 0; o < 3; o++)
                #pragma unroll
                for (int t = 0; t < 9; t++)
                    wf[o][t] = s_w[ic][o][8 - t];
            #pragma unroll
            for (int t = 0; t < 9; t++) {
                const int ky = t / 3, kx = t % 3;
                #pragma unroll
                for (int r = 0; r < 4; r++)
                    #pragma unroll
                    for (int c = 0; c < 2; c++) {
                        float vv = v[r + ky][c + kx];
                        #pragma unroll
                        for (int o = 0; o < 3; o++)
                            acc[r][c][o] = fmaf(vv, wf[o][t], acc[r][c][o]);
                    }
            }
        }
    }

    #pragma unroll
    for (int o = 0; o < 3; o++) {
        float bs = bias[o];
        #pragma unroll
        for (int r = 0; r < 4; r++)
            #pragma unroll
            for (int c = 0; c < 2; c++) {
                int oy = oy0 + py * 4 + r, ox = ox0 + px * 2 + c;
                out[((size_t)b * 3 + o) * 4096 + oy * 64 + ox] =
                    0.5f + 0.5f * tanhf(acc[r][c][o] + bs);
            }
    }
}

// =================================================================
// 64x64 register-blocked GEMM (full K), + bias/act.
// =================================================================
__global__ void gemm64(const float* __restrict__ A, const float* __restrict__ Wt,
                       const float* __restrict__ bias, float* __restrict__ C,
                       int M, int N, int K, int ldc, int act)
{
    __shared__ float sA[64][17];
    __shared__ float sB[64][17];
    const int tid = threadIdx.x;
    const int tx = tid % 16, ty = tid / 16;
    const int m0 = blockIdx.y * 64, n0 = blockIdx.x * 64;

    float acc[4][4];
    #pragma unroll
    for (int i = 0; i < 4; i++)
        #pragma unroll
        for (int j = 0; j < 4; j++) acc[i][j] = 0.f;

    for (int k0 = 0; k0 < K; k0 += 16) {
        __syncthreads();
        #pragma unroll
        for (int l = 0; l < 4; l++) {
            int i = tid + l * 256;
            int r = i / 16, c = i % 16;
            sA[r][c] = A[(size_t)(m0 + r) * K + k0 + c];
            sB[r][c] = Wt[(size_t)(n0 + r) * K + k0 + c];
        }
        __syncthreads();
        #pragma unroll
        for (int kk = 0; kk < 16; kk++) {
            float a[4], bb[4];
            #pragma unroll
            for (int i = 0; i < 4; i++) a[i] = sA[ty * 4 + i][kk];
            #pragma unroll
            for (int j = 0; j < 4; j++) bb[j] = sB[tx * 4 + j][kk];
            #pragma unroll
            for (int i = 0; i < 4; i++)
                #pragma unroll
                for (int j = 0; j < 4; j++)
                    acc[i][j] = fmaf(a[i], bb[j], acc[i][j]);
        }
    }
    #pragma unroll
    for (int i = 0; i < 4; i++) {
        int m = m0 + ty * 4 + i;
        #pragma unroll
        for (int j = 0; j < 4; j++) {
            int n = n0 + tx * 4 + j;
            float r = acc[i][j];
            if (bias) r += bias[n];
            if (act == 1) r = fmaxf(r, 0.f);
            C[(size_t)m * ldc + n] = r;
        }
    }
}

// =================================================================
// FC heads, deterministic split-K: partials to `part`, fused BN on A.
// =================================================================
__global__ void gemm_heads_splitk(const float* __restrict__ A,
                                  const float* __restrict__ Wmu,
                                  const float* __restrict__ Wcov,
                                  float* __restrict__ part, int KS)
{
    __shared__ float sA[64][17];
    __shared__ float sB[64][17];
    const int tid = threadIdx.x;
    const int tx = tid % 16, ty = tid / 16;
    const int m0 = blockIdx.y * 64, n0 = blockIdx.x * 64;
    const float* Wt = (n0 < 128) ? (Wmu + (size_t)n0 * 4096) : (Wcov + (size_t)(n0 - 128) * 4096);
    const int kbase = blockIdx.z * KS;

    float acc[4][4];
    #pragma unroll
    for (int i = 0; i < 4; i++)
        #pragma unroll
        for (int j = 0; j < 4; j++) acc[i][j] = 0.f;

    for (int k0 = kbase; k0 < kbase + KS; k0 += 16) {
        __syncthreads();
        #pragma unroll
        for (int l = 0; l < 4; l++) {
            int i = tid + l * 256;
            int r = i / 16, c = i % 16;
            int k = k0 + c;
            int ch = k >> 4;
            sA[r][c] = (A[(size_t)(m0 + r) * 4096 + k] - g_mean[ch]) * g_rstd[ch];
            sB[r][c] = Wt[(size_t)r * 4096 + k];
        }
        __syncthreads();
        #pragma unroll
        for (int kk = 0; kk < 16; kk++) {
            float a[4], bb[4];
            #pragma unroll
            for (int i = 0; i < 4; i++) a[i] = sA[ty * 4 + i][kk];
            #pragma unroll
            for (int j = 0; j < 4; j++) bb[j] = sB[tx * 4 + j][kk];
            #pragma unroll
            for (int i = 0; i < 4; i++)
                #pragma unroll
                for (int j = 0; j < 4; j++)
                    acc[i][j] = fmaf(a[i], bb[j], acc[i][j]);
        }
    }
    #pragma unroll
    for (int i = 0; i < 4; i++) {
        int m = m0 + ty * 4 + i;
        #pragma unroll
        for (int j = 0; j < 4; j++) {
            int n = n0 + tx * 4 + j;
            part[((size_t)blockIdx.z * 256 + m) * 256 + n] = acc[i][j];
        }
    }
}

__global__ void head_combine(const float* __restrict__ part,
                             const float* __restrict__ bmu,
                             const float* __restrict__ bcov, int Z)
{
    int m = blockIdx.x, n = threadIdx.x;
    float s = 0.f;
    for (int z = 0; z < Z; z++) s += part[((size_t)z * 256 + m) * 256 + n];
    if (n < 128) s += bmu[n];
    else { s += bcov[n - 128]; s = fmaxf(s, 0.f); }
    g_ze[m * 256 + n] = s;
}

// ---------------- codebook norms + zero loss ----------------
__global__ void cnorm_k(const float* __restrict__ cb)
{
    int gwarp = (blockIdx.x * blockDim.x + threadIdx.x) >> 5;
    int lane = threadIdx.x & 31;
    if (gwarp < 8192) {
        const float* p = cb + (size_t)gwarp * 256;
        float s = 0.f;
        for (int d = lane; d < 256; d += 32) { float v = p[d]; s = fmaf(v, v, s); }
        #pragma unroll
        for (int o = 16; o; o >>= 1) s += __shfl_xor_sync(0xffffffffu, s, o);
        if (lane == 0) g_cnorm[gwarp] = s;
    }
    if (blockIdx.x == 0 && threadIdx.x == 0) g_loss = 0.0;
}

// ---------------- VQ argmin + gather + loss ----------------
__global__ void vq_argmin(const float* __restrict__ S, const float* __restrict__ cb)
{
    int b = blockIdx.x;
    int tid = threadIdx.x;
    float best = INFINITY; int bi = 0x7fffffff;
    const float* Sb = S + (size_t)b * 8192;
    for (int k = tid; k < 8192; k += 256) {
        float d = g_cnorm[k] - 2.f * Sb[k];
        if (d < best || (d == best && k < bi)) { best = d; bi = k; }
    }
    __shared__ float sv[256];
    __shared__ int   si[256];
    sv[tid] = best; si[tid] = bi;
    __syncthreads();
    for (int st = 128; st > 0; st >>= 1) {
        if (tid < st) {
            if (sv[tid + st] < sv[tid] ||
               (sv[tid + st] == sv[tid] && si[tid + st] < si[tid])) {
                sv[tid] = sv[tid + st]; si[tid] = si[tid + st];
            }
        }
        __syncthreads();
    }
    int idx = si[0];
    float cv = cb[(size_t)idx * 256 + tid];
    float diff = g_ze[b * 256 + tid] - cv;
    g_zq[b * 256 + tid] = cv;
    __shared__ double sl[256];
    sl[tid] = (double)diff * diff;
    __syncthreads();
    for (int st = 128; st > 0; st >>= 1) {
        if (tid < st) sl[tid] += sl[tid + st];
        __syncthreads();
    }
    if (tid == 0) atomicAdd(&g_loss, sl[0]);
}

__global__ void write_loss(float* out, long long pos)
{
    out[pos] = (float)(2.0 * g_loss);
}

// ---------------- host orchestration ----------------
extern "C" void kernel_launch(void* const* d_in, const int* in_sizes, int n_in,
                              void* d_out, int out_size)
{
    const float* x     = (const float*)d_in[0];
    const float* ew1   = (const float*)d_in[1];
    const float* eb1   = (const float*)d_in[2];
    const float* ew2   = (const float*)d_in[3];
    const float* eb2   = (const float*)d_in[4];
    const float* ew3   = (const float*)d_in[5];
    const float* eb3   = (const float*)d_in[6];
    const float* ew4   = (const float*)d_in[7];
    const float* eb4   = (const float*)d_in[8];
    const float* ewmu  = (const float*)d_in[9];
    const float* ebmu  = (const float*)d_in[10];
    const float* ewcov = (const float*)d_in[11];
    const float* ebcov = (const float*)d_in[12];
    const float* cb    = (const float*)d_in[13];
    const float* dwfc  = (const float*)d_in[14];
    const float* dbfc  = (const float*)d_in[15];
    const float* dwt1  = (const float*)d_in[16];
    const float* dbt1  = (const float*)d_in[17];
    const float* dwt2  = (const float*)d_in[18];
    const float* dbt2  = (const float*)d_in[19];
    const float* dwt3  = (const float*)d_in[20];
    const float* dbt3  = (const float*)d_in[21];
    const float* dwt31 = (const float*)d_in[22];
    const float* dbt31 = (const float*)d_in[23];
    const float* dwt4  = (const float*)d_in[24];
    const float* dbt4  = (const float*)d_in[25];
    float* out = (float*)d_out;

    float *A, *Bf, *ze, *zq, *gm, *gr;
    cudaGetSymbolAddress((void**)&A,  g_bufA);
    cudaGetSymbolAddress((void**)&Bf, g_bufB);
    cudaGetSymbolAddress((void**)&ze, g_ze);
    cudaGetSymbolAddress((void**)&zq, g_zq);
    cudaGetSymbolAddress((void**)&gm, g_mean);
    cudaGetSymbolAddress((void**)&gr, g_rstd);

    init_zero<<<1, 256>>>();

    // ---- Encoder (BN stats fused into conv epilogues) ----
    conv3s2<3, 64, 64, 32, 16, 16, 1, 32, 8, 3>
        <<<dim3(1024, 1), 256>>>(x, ew1, eb1, nullptr, nullptr, Bf);
    bn_finalize<<<1, 256>>>(32, 1.f / (256.f * 1024.f));

    conv3s2<32, 32, 32, 64, 16, 16, 1, 64, 16, 4>
        <<<dim3(256, 1), 256>>>(Bf, ew2, eb2, gm, gr, A);
    bn_finalize<<<1, 256>>>(64, 1.f / (256.f * 256.f));

    conv3s2<64, 16, 16, 128, 8, 8, 1, 128, 8, 8>
        <<<dim3(256, 1), 256>>>(A, ew3, eb3, gm, gr, Bf);
    bn_finalize<<<1, 256>>>(128, 1.f / (256.f * 64.f));

    conv3s2<128, 8, 8, 256, 4, 4, 2, 128, 8, 8>
        <<<dim3(128, 2), 128>>>(Bf, ew4, eb4, gm, gr, A);
    bn_finalize<<<1, 256>>>(256, 1.f / (256.f * 16.f));

    // ---- FC heads (split-K, BN4 fused), partials in Bf ----
    gemm_heads_splitk<<<dim3(4, 4, 8), 256>>>(A, ewmu, ewcov, Bf, 512);
    head_combine<<<256, 256>>>(Bf, ebmu, ebcov, 8);

    // ---- VQ ----
    cnorm_k<<<1024, 256>>>(cb);
    gemm64<<<dim3(128, 4), 256>>>(ze, cb, nullptr, Bf, 256, 8192, 256, 8192, 0);
    vq_argmin<<<BATCH, 256>>>(Bf, cb);

    // ---- Decoder FC ----
    gemm64<<<dim3(64, 4), 256>>>(zq, dwfc, dbfc, A, 256, 4096, 256, 4096, 0);

    // ---- Decoder (BN stats fused into convT epilogues) ----
    convt3s2<256, 4, 4, 128, 8, 8, 2, 64, 4, 16>
        <<<dim3(128, 2), 128>>>(A, dwt1, dbt1, nullptr, nullptr, Bf);
    bn_finalize<<<1, 256>>>(128, 1.f / (256.f * 64.f));

    convt3s2<128, 8, 8, 64, 16, 16, 1, 64, 4, 16>
        <<<dim3(256, 1), 256>>>(Bf, dwt2, dbt2, gm, gr, A);
    bn_finalize<<<1, 256>>>(64, 1.f / (256.f * 256.f));

    convt3s2<64, 16, 16, 32, 32, 32, 1, 32, 4, 16>
        <<<dim3(256, 1), 512>>>(A, dwt3, dbt3, gm, gr, Bf);
    bn_finalize<<<1, 256>>>(32, 1.f / (256.f * 1024.f));

    convt3s2<32, 32, 32, 32, 32, 32, 1, 32, 4, 16>
        <<<dim3(1024, 1), 512>>>(Bf, dwt31, dbt31, gm, gr, A);
    bn_finalize<<<1, 256>>>(32, 1.f / (256.f * 4096.f));

    convt4_s1_tanh<<<dim3(1024, 1), 128>>>(A, dwt4, dbt4, gm, gr, out);

    // ---- scalar vq_loss ----
    write_loss<<<1, 1>>>(out, (long long)out_size - 1);
}

// round 8
// speedup vs baseline: 1.1676x; 1.0265x over previous
#include <cuda_runtime.h>
#include <math.h>

#define BATCH 256
#define SLOPE 0.01f

typedef unsigned long long u64;

// packed fp32x2 helpers (sm_100+): 2 fp32 FMAs per issued instruction, bit-exact
#define FMA_F32X2(d, a, b) \
    asm("fma.rn.f32x2 %0, %1, %2, %0;" : "+l"(d) : "l"(a), "l"(b))
#define PACK2(u, lo, hi) \
    asm("mov.b64 %0, {%1, %2};" : "=l"(u) : "f"(lo), "f"(hi))
#define UNPACK2(lo, hi, u) \
    asm("mov.b64 {%0, %1}, %2;" : "=f"(lo), "=f"(hi) : "l"(u))

// ---------------- static scratch ----------------
__device__ float    g_bufA[33554432];   // 134 MB
__device__ float    g_bufB[8388608];    // 33.5 MB
__device__ float    g_ze[BATCH * 256];
__device__ float    g_zq[BATCH * 256];
__device__ float    g_cnorm[8192];
__device__ double   g_sum[256];
__device__ double   g_sumsq[256];
__device__ float    g_mean[256];
__device__ float    g_rstd[256];
__device__ double   g_loss;

__global__ void init_zero()
{
    int i = threadIdx.x;
    g_sum[i] = 0.0; g_sumsq[i] = 0.0;
}

__global__ void bn_finalize(int C, float invn)
{
    int c = threadIdx.x;
    if (c < C) {
        double mu  = g_sum[c] * (double)invn;
        double var = g_sumsq[c] * (double)invn - mu * mu;
        g_mean[c] = (float)mu;
        g_rstd[c] = (float)rsqrt(var + 1e-5);
        g_sum[c] = 0.0; g_sumsq[c] = 0.0;
    }
}

// =================================================================
// Direct conv 3x3 s2 p1 + bias + LeakyReLU, fused input BN + output BN stats.
// f32x2: accumulators pair adjacent output channels; weights fetched as LDS.64.
// =================================================================
template<int CIN, int HIN, int WIN, int COUT, int OTH, int OTW,
         int BB, int OCB, int OCT, int CC>
__global__ void conv3s2(const float* __restrict__ in, const float* __restrict__ gw,
                        const float* __restrict__ bias,
                        const float* __restrict__ nmean, const float* __restrict__ nrstd,
                        float* __restrict__ out)
{
    constexpr int HOUT = HIN / 2, WOUT = WIN / 2;
    constexpr int S    = (OTH / 2) * (OTW / 2);
    constexpr int G    = OCB / OCT;
    constexpr int BLK  = BB * S * G;
    constexpr int ITH  = 2 * OTH + 1, ITW = 2 * OTW + 1;
    constexpr int JP   = OCT / 2;
    constexpr int TPC  = BB * S;
    constexpr int SEG  = (TPC >= 32) ? 32 : TPC;
    __shared__ float s_in[BB][CC][ITH][ITW];
    __shared__ u64   s_w2[CC * 9 * (OCB / 2)];
    __shared__ float sh_bns[OCB], sh_bns2[OCB];

    const int tid = threadIdx.x;
    const int sp  = tid % S;
    const int ib  = (tid / S) % BB;
    const int og  = tid / (S * BB);
    const int sy  = sp / (OTW / 2), sx = sp % (OTW / 2);

    constexpr int TX = WOUT / OTW, TY = HOUT / OTH;
    const int tile = blockIdx.x % (TX * TY);
    const int imgc = blockIdx.x / (TX * TY);
    const int tcx = tile % TX, tcy = tile / TX;
    const int ocBase = blockIdx.y * OCB;
    const int oy0 = tcy * OTH, ox0 = tcx * OTW;
    const int iy0 = oy0 * 2 - 1, ix0 = ox0 * 2 - 1;
    const bool donorm = (nmean != nullptr);

    for (int i = tid; i < OCB; i += BLK) { sh_bns[i] = 0.f; sh_bns2[i] = 0.f; }

    u64 acc2[2][2][JP];
    #pragma unroll
    for (int dy = 0; dy < 2; dy++)
        #pragma unroll
        for (int dx = 0; dx < 2; dx++)
            #pragma unroll
            for (int j = 0; j < JP; j++) acc2[dy][dx][j] = 0ull;

    float* wf = (float*)s_w2;

    for (int c0 = 0; c0 < CIN; c0 += CC) {
        __syncthreads();
        for (int i = tid; i < BB * CC * ITH * ITW; i += BLK) {
            int lb = i / (CC * ITH * ITW);
            int r2 = i % (CC * ITH * ITW);
            int ic = r2 / (ITH * ITW);
            int r  = (r2 / ITW) % ITH;
            int cc = r2 % ITW;
            int gy = iy0 + r, gx = ix0 + cc;
            float v = 0.f;
            if (gy >= 0 && gy < HIN && gx >= 0 && gx < WIN) {
                v = in[((size_t)(imgc * BB + lb) * CIN + c0 + ic) * (HIN * WIN) + gy * WIN + gx];
                if (donorm) v = (v - nmean[c0 + ic]) * nrstd[c0 + ic];
            }
            s_in[lb][ic][r][cc] = v;
        }
        // weights: gw[oc][ci][t] -> wf[(ic*9+t)*OCB + o]  (oc contiguous for LDS.64 pairs)
        for (int i = tid; i < OCB * CC * 9; i += BLK) {
            int o = i / (CC * 9);
            int rem = i % (CC * 9);
            int ic = rem / 9, t = rem % 9;
            wf[(ic * 9 + t) * OCB + o] = gw[((size_t)(ocBase + o) * CIN + c0) * 9 + rem];
        }
        __syncthreads();

        for (int ic = 0; ic < CC; ic++) {
            #pragma unroll
            for (int t = 0; t < 9; t++) {
                const int ky = t / 3, kx = t % 3;
                u64 w2[JP];
                const u64* wp = s_w2 + (ic * 9 + t) * (OCB / 2) + og * JP;
                #pragma unroll
                for (int j = 0; j < JP; j++) w2[j] = wp[j];
                #pragma unroll
                for (int dy = 0; dy < 2; dy++)
                    #pragma unroll
                    for (int dx = 0; dx < 2; dx++) {
                        float v = s_in[ib][ic][sy * 4 + dy * 2 + ky][sx * 4 + dx * 2 + kx];
                        u64 v2; PACK2(v2, v, v);
                        #pragma unroll
                        for (int j = 0; j < JP; j++)
                            FMA_F32X2(acc2[dy][dx][j], v2, w2[j]);
                    }
            }
        }
    }

    const int b = imgc * BB + ib;
    #pragma unroll
    for (int jp = 0; jp < JP; jp++) {
        #pragma unroll
        for (int h = 0; h < 2; h++) {
            int oc = ocBase + og * OCT + 2 * jp + h;
            float bs = bias[oc];
            float sj = 0.f, s2j = 0.f;
            #pragma unroll
            for (int dy = 0; dy < 2; dy++)
                #pragma unroll
                for (int dx = 0; dx < 2; dx++) {
                    float lo, hi; UNPACK2(lo, hi, acc2[dy][dx][jp]);
                    float r = (h == 0 ? lo : hi) + bs;
                    r = r >= 0.f ? r : SLOPE * r;
                    int oy = oy0 + sy * 2 + dy, ox = ox0 + sx * 2 + dx;
                    out[((size_t)b * COUT + oc) * (HOUT * WOUT) + oy * WOUT + ox] = r;
                    sj += r; s2j = fmaf(r, r, s2j);
                }
            #pragma unroll
            for (int o = SEG / 2; o; o >>= 1) {
                sj  += __shfl_down_sync(0xffffffffu, sj,  o, SEG);
                s2j += __shfl_down_sync(0xffffffffu, s2j, o, SEG);
            }
            if ((tid & (SEG - 1)) == 0) {
                atomicAdd(&sh_bns[og * OCT + 2 * jp + h],  sj);
                atomicAdd(&sh_bns2[og * OCT + 2 * jp + h], s2j);
            }
        }
    }
    __syncthreads();
    for (int i = tid; i < OCB; i += BLK) {
        atomicAdd(&g_sum[ocBase + i],   (double)sh_bns[i]);
        atomicAdd(&g_sumsq[ocBase + i], (double)sh_bns2[i]);
    }
}

// =================================================================
// convT 3x3 s2 p1 op1 + bias + LeakyReLU, fused input BN + output BN stats.
// f32x2 over oc pairs; 4x4 output tile per thread.
// =================================================================
template<int CIN, int HIN, int WIN, int COUT, int OTH, int OTW,
         int BB, int OCB, int OCT, int CC>
__global__ void convt3s2(const float* __restrict__ in, const float* __restrict__ gw,
                         const float* __restrict__ bias,
                         const float* __restrict__ nmean, const float* __restrict__ nrstd,
                         float* __restrict__ out)
{
    constexpr int HOUT = 2 * HIN, WOUT = 2 * WIN;
    constexpr int SP   = (OTH / 4) * (OTW / 4);
    constexpr int G    = OCB / OCT;
    constexpr int BLK  = BB * SP * G;
    constexpr int ITH  = OTH / 2 + 1, ITW = OTW / 2 + 1;
    constexpr int JP   = OCT / 2;
    constexpr int TPC  = BB * SP;
    constexpr int SEG  = (TPC >= 32) ? 32 : TPC;
    __shared__ float s_in[BB][CC][ITH][ITW];
    __shared__ u64   s_w2[CC * 9 * (OCB / 2)];
    __shared__ float sh_bns[OCB], sh_bns2[OCB];

    const int tid = threadIdx.x;
    const int sp  = tid % SP;
    const int ib  = (tid / SP) % BB;
    const int og  = tid / (SP * BB);
    const int ty  = sp / (OTW / 4), tx = sp % (OTW / 4);

    constexpr int TX = WOUT / OTW, TY = HOUT / OTH;
    const int tile = blockIdx.x % (TX * TY);
    const int imgc = blockIdx.x / (TX * TY);
    const int tcx = tile % TX, tcy = tile / TX;
    const int ocBase = blockIdx.y * OCB;
    const int oy0 = tcy * OTH, ox0 = tcx * OTW;
    const int iy0 = oy0 / 2, ix0 = ox0 / 2;
    const bool donorm = (nmean != nullptr);

    for (int i = tid; i < OCB; i += BLK) { sh_bns[i] = 0.f; sh_bns2[i] = 0.f; }

    u64 acc2[4][4][JP];
    #pragma unroll
    for (int r = 0; r < 4; r++)
        #pragma unroll
        for (int c = 0; c < 4; c++)
            #pragma unroll
            for (int j = 0; j < JP; j++) acc2[r][c][j] = 0ull;

    float* wf = (float*)s_w2;

    for (int c0 = 0; c0 < CIN; c0 += CC) {
        __syncthreads();
        for (int i = tid; i < BB * CC * ITH * ITW; i += BLK) {
            int lb = i / (CC * ITH * ITW);
            int r2 = i % (CC * ITH * ITW);
            int ic = r2 / (ITH * ITW);
            int r  = (r2 / ITW) % ITH;
            int cc = r2 % ITW;
            int gy = iy0 + r, gx = ix0 + cc;
            float v = 0.f;
            if (gy < HIN && gx < WIN) {
                v = in[((size_t)(imgc * BB + lb) * CIN + c0 + ic) * (HIN * WIN) + gy * WIN + gx];
                if (donorm) v = (v - nmean[c0 + ic]) * nrstd[c0 + ic];
            }
            s_in[lb][ic][r][cc] = v;
        }
        // weights: gw[ci][oc][t] -> wf[(ic*9+t)*OCB + o]
        for (int i = tid; i < CC * OCB * 9; i += BLK) {
            int ic = i / (OCB * 9);
            int r2 = i % (OCB * 9);
            int o = r2 / 9, t = r2 % 9;
            wf[(ic * 9 + t) * OCB + o] = gw[((size_t)(c0 + ic) * COUT + ocBase) * 9 + r2];
        }
        __syncthreads();

        for (int ic = 0; ic < CC; ic++) {
            u64 v2[3][3];
            #pragma unroll
            for (int a = 0; a < 3; a++)
                #pragma unroll
                for (int bb2 = 0; bb2 < 3; bb2++) {
                    float v = s_in[ib][ic][2 * ty + a][2 * tx + bb2];
                    PACK2(v2[a][bb2], v, v);
                }
            #pragma unroll
            for (int j = 0; j < JP; j++) {
                u64 w2[9];
                #pragma unroll
                for (int q = 0; q < 9; q++)
                    w2[q] = s_w2[(ic * 9 + q) * (OCB / 2) + og * JP + j];
                #pragma unroll
                for (int cy = 0; cy < 2; cy++)
                    #pragma unroll
                    for (int cx = 0; cx < 2; cx++) {
                        FMA_F32X2(acc2[2*cy  ][2*cx  ][j], w2[4], v2[cy][cx]);
                        FMA_F32X2(acc2[2*cy  ][2*cx+1][j], w2[3], v2[cy][cx+1]);
                        FMA_F32X2(acc2[2*cy  ][2*cx+1][j], w2[5], v2[cy][cx]);
                        FMA_F32X2(acc2[2*cy+1][2*cx  ][j], w2[1], v2[cy+1][cx]);
                        FMA_F32X2(acc2[2*cy+1][2*cx  ][j], w2[7], v2[cy][cx]);
                        FMA_F32X2(acc2[2*cy+1][2*cx+1][j], w2[0], v2[cy+1][cx+1]);
                        FMA_F32X2(acc2[2*cy+1][2*cx+1][j], w2[2], v2[cy+1][cx]);
                        FMA_F32X2(acc2[2*cy+1][2*cx+1][j], w2[6], v2[cy][cx+1]);
                        FMA_F32X2(acc2[2*cy+1][2*cx+1][j], w2[8], v2[cy][cx]);
                    }
            }
        }
    }

    const int b = imgc * BB + ib;
    #pragma unroll
    for (int jp = 0; jp < JP; jp++) {
        #pragma unroll
        for (int h = 0; h < 2; h++) {
            int oc = ocBase + og * OCT + 2 * jp + h;
            float bs = bias[oc];
            float sj = 0.f, s2j = 0.f;
            #pragma unroll
            for (int r = 0; r < 4; r++)
                #pragma unroll
                for (int c = 0; c < 4; c++) {
                    float lo, hi; UNPACK2(lo, hi, acc2[r][c][jp]);
                    float rv = (h == 0 ? lo : hi) + bs;
                    rv = rv >= 0.f ? rv : SLOPE * rv;
                    int oy = oy0 + 4 * ty + r, ox = ox0 + 4 * tx + c;
                    out[((size_t)b * COUT + oc) * (HOUT * WOUT) + oy * WOUT + ox] = rv;
                    sj += rv; s2j = fmaf(rv, rv, s2j);
                }
            #pragma unroll
            for (int o = SEG / 2; o; o >>= 1) {
                sj  += __shfl_down_sync(0xffffffffu, sj,  o, SEG);
                s2j += __shfl_down_sync(0xffffffffu, s2j, o, SEG);
            }
            if ((tid & (SEG - 1)) == 0) {
                atomicAdd(&sh_bns[og * OCT + 2 * jp + h],  sj);
                atomicAdd(&sh_bns2[og * OCT + 2 * jp + h], s2j);
            }
        }
    }
    __syncthreads();
    for (int i = tid; i < OCB; i += BLK) {
        atomicAdd(&g_sum[ocBase + i],   (double)sh_bns[i]);
        atomicAdd(&g_sumsq[ocBase + i], (double)sh_bns2[i]);
    }
}

// =================================================================
// Final convT (s1 p1) + tanh head. f32x2 over the 2 output columns per thread.
// Weights pre-flipped AND pre-duplicated {w,w} in smem.
// =================================================================
__global__ void __launch_bounds__(128)
convt4_s1_tanh(const float* __restrict__ in, const float* __restrict__ gw,
               const float* __restrict__ bias,
               const float* __restrict__ nmean, const float* __restrict__ nrstd,
               float* __restrict__ out)
{
    __shared__ float s_in[8][34][34];
    __shared__ u64   s_w2[8][3][9];   // {w,w} duplicated, tap-flipped
    const int tid = threadIdx.x;             // 128
    const int py = tid / 16, px = tid % 16;  // each thread: 4 rows x 2 cols
    const int bx = blockIdx.x;
    const int tcx = bx % 2, tcy = (bx / 2) % 2, b = bx / 4;
    const int oy0 = tcy * 32, ox0 = tcx * 32;

    u64 acc2[4][3];
    #pragma unroll
    for (int r = 0; r < 4; r++)
        #pragma unroll
        for (int o = 0; o < 3; o++) acc2[r][o] = 0ull;

    for (int c0 = 0; c0 < 32; c0 += 8) {
        __syncthreads();
        for (int i = tid; i < 8 * 34 * 34; i += 128) {
            int ic = i / 1156, r = (i / 34) % 34, c = i % 34;
            int gy = oy0 - 1 + r, gx = ox0 - 1 + c;
            float v = 0.f;
            if (gy >= 0 && gy < 64 && gx >= 0 && gx < 64)
                v = (in[((size_t)b * 32 + c0 + ic) * 4096 + gy * 64 + gx]
                     - nmean[c0 + ic]) * nrstd[c0 + ic];
            s_in[ic][r][c] = v;
        }
        for (int i = tid; i < 8 * 27; i += 128) {
            int ic = i / 27, rem = i % 27;
            int o = rem / 9, t = rem % 9;
            float w = gw[(c0 + ic) * 27 + o * 9 + t];
            float* p = (float*)&s_w2[ic][o][8 - t];
            p[0] = w; p[1] = w;
        }
        __syncthreads();

        for (int ic = 0; ic < 8; ic++) {
            float v[6][4];
            #pragma unroll
            for (int r = 0; r < 6; r++)
                #pragma unroll
                for (int c = 0; c < 4; c++)
                    v[r][c] = s_in[ic][py * 4 + r][px * 2 + c];
            u64 p2[6][3];
            #pragma unroll
            for (int r = 0; r < 6; r++)
                #pragma unroll
                for (int k = 0; k < 3; k++)
                    PACK2(p2[r][k], v[r][k], v[r][k + 1]);
            #pragma unroll
            for (int t = 0; t < 9; t++) {
                const int ky = t / 3, kx = t % 3;
                u64 w0 = s_w2[ic][0][t];
                u64 w1 = s_w2[ic][1][t];
                u64 w2 = s_w2[ic][2][t];
                #pragma unroll
                for (int r = 0; r < 4; r++) {
                    FMA_F32X2(acc2[r][0], p2[r + ky][kx], w0);
                    FMA_F32X2(acc2[r][1], p2[r + ky][kx], w1);
                    FMA_F32X2(acc2[r][2], p2[r + ky][kx], w2);
                }
            }
        }
    }

    #pragma unroll
    for (int o = 0; o < 3; o++) {
        float bs = bias[o];
        #pragma unroll
        for (int r = 0; r < 4; r++) {
            float lo, hi; UNPACK2(lo, hi, acc2[r][o]);
            int oy = oy0 + py * 4 + r, ox = ox0 + px * 2;
            size_t base = ((size_t)b * 3 + o) * 4096 + oy * 64 + ox;
            out[base]     = 0.5f + 0.5f * tanhf(lo + bs);
            out[base + 1] = 0.5f + 0.5f * tanhf(hi + bs);
        }
    }
}

// =================================================================
// 64x64 register-blocked GEMM (full K), + bias/act.
// =================================================================
__global__ void gemm64(const float* __restrict__ A, const float* __restrict__ Wt,
                       const float* __restrict__ bias, float* __restrict__ C,
                       int M, int N, int K, int ldc, int act)
{
    __shared__ float sA[64][17];
    __shared__ float sB[64][17];
    const int tid = threadIdx.x;
    const int tx = tid % 16, ty = tid / 16;
    const int m0 = blockIdx.y * 64, n0 = blockIdx.x * 64;

    float acc[4][4];
    #pragma unroll
    for (int i = 0; i < 4; i++)
        #pragma unroll
        for (int j = 0; j < 4; j++) acc[i][j] = 0.f;

    for (int k0 = 0; k0 < K; k0 += 16) {
        __syncthreads();
        #pragma unroll
        for (int l = 0; l < 4; l++) {
            int i = tid + l * 256;
            int r = i / 16, c = i % 16;
            sA[r][c] = A[(size_t)(m0 + r) * K + k0 + c];
            sB[r][c] = Wt[(size_t)(n0 + r) * K + k0 + c];
        }
        __syncthreads();
        #pragma unroll
        for (int kk = 0; kk < 16; kk++) {
            float a[4], bb[4];
            #pragma unroll
            for (int i = 0; i < 4; i++) a[i] = sA[ty * 4 + i][kk];
            #pragma unroll
            for (int j = 0; j < 4; j++) bb[j] = sB[tx * 4 + j][kk];
            #pragma unroll
            for (int i = 0; i < 4; i++)
                #pragma unroll
                for (int j = 0; j < 4; j++)
                    acc[i][j] = fmaf(a[i], bb[j], acc[i][j]);
        }
    }
    #pragma unroll
    for (int i = 0; i < 4; i++) {
        int m = m0 + ty * 4 + i;
        #pragma unroll
        for (int j = 0; j < 4; j++) {
            int n = n0 + tx * 4 + j;
            float r = acc[i][j];
            if (bias) r += bias[n];
            if (act == 1) r = fmaxf(r, 0.f);
            C[(size_t)m * ldc + n] = r;
        }
    }
}

// =================================================================
// FC heads, deterministic split-K: partials to `part`, fused BN on A.
// =================================================================
__global__ void gemm_heads_splitk(const float* __restrict__ A,
                                  const float* __restrict__ Wmu,
                                  const float* __restrict__ Wcov,
                                  float* __restrict__ part, int KS)
{
    __shared__ float sA[64][17];
    __shared__ float sB[64][17];
    const int tid = threadIdx.x;
    const int tx = tid % 16, ty = tid / 16;
    const int m0 = blockIdx.y * 64, n0 = blockIdx.x * 64;
    const float* Wt = (n0 < 128) ? (Wmu + (size_t)n0 * 4096) : (Wcov + (size_t)(n0 - 128) * 4096);
    const int kbase = blockIdx.z * KS;

    float acc[4][4];
    #pragma unroll
    for (int i = 0; i < 4; i++)
        #pragma unroll
        for (int j = 0; j < 4; j++) acc[i][j] = 0.f;

    for (int k0 = kbase; k0 < kbase + KS; k0 += 16) {
        __syncthreads();
        #pragma unroll
        for (int l = 0; l < 4; l++) {
            int i = tid + l * 256;
            int r = i / 16, c = i % 16;
            int k = k0 + c;
            int ch = k >> 4;
            sA[r][c] = (A[(size_t)(m0 + r) * 4096 + k] - g_mean[ch]) * g_rstd[ch];
            sB[r][c] = Wt[(size_t)r * 4096 + k];
        }
        __syncthreads();
        #pragma unroll
        for (int kk = 0; kk < 16; kk++) {
            float a[4], bb[4];
            #pragma unroll
            for (int i = 0; i < 4; i++) a[i] = sA[ty * 4 + i][kk];
            #pragma unroll
            for (int j = 0; j < 4; j++) bb[j] = sB[tx * 4 + j][kk];
            #pragma unroll
            for (int i = 0; i < 4; i++)
                #pragma unroll
                for (int j = 0; j < 4; j++)
                    acc[i][j] = fmaf(a[i], bb[j], acc[i][j]);
        }
    }
    #pragma unroll
    for (int i = 0; i < 4; i++) {
        int m = m0 + ty * 4 + i;
        #pragma unroll
        for (int j = 0; j < 4; j++) {
            int n = n0 + tx * 4 + j;
            part[((size_t)blockIdx.z * 256 + m) * 256 + n] = acc[i][j];
        }
    }
}

__global__ void head_combine(const float* __restrict__ part,
                             const float* __restrict__ bmu,
                             const float* __restrict__ bcov, int Z)
{
    int m = blockIdx.x, n = threadIdx.x;
    float s = 0.f;
    for (int z = 0; z < Z; z++) s += part[((size_t)z * 256 + m) * 256 + n];
    if (n < 128) s += bmu[n];
    else { s += bcov[n - 128]; s = fmaxf(s, 0.f); }
    g_ze[m * 256 + n] = s;
}

// ---------------- codebook norms + zero loss ----------------
__global__ void cnorm_k(const float* __restrict__ cb)
{
    int gwarp = (blockIdx.x * blockDim.x + threadIdx.x) >> 5;
    int lane = threadIdx.x & 31;
    if (gwarp < 8192) {
        const float* p = cb + (size_t)gwarp * 256;
        float s = 0.f;
        for (int d = lane; d < 256; d += 32) { float v = p[d]; s = fmaf(v, v, s); }
        #pragma unroll
        for (int o = 16; o; o >>= 1) s += __shfl_xor_sync(0xffffffffu, s, o);
        if (lane == 0) g_cnorm[gwarp] = s;
    }
    if (blockIdx.x == 0 && threadIdx.x == 0) g_loss = 0.0;
}

// ---------------- VQ argmin + gather + loss ----------------
__global__ void vq_argmin(const float* __restrict__ S, const float* __restrict__ cb)
{
    int b = blockIdx.x;
    int tid = threadIdx.x;
    float best = INFINITY; int bi = 0x7fffffff;
    const float* Sb = S + (size_t)b * 8192;
    for (int k = tid; k < 8192; k += 256) {
        float d = g_cnorm[k] - 2.f * Sb[k];
        if (d < best || (d == best && k < bi)) { best = d; bi = k; }
    }
    __shared__ float sv[256];
    __shared__ int   si[256];
    sv[tid] = best; si[tid] = bi;
    __syncthreads();
    for (int st = 128; st > 0; st >>= 1) {
        if (tid < st) {
            if (sv[tid + st] < sv[tid] ||
               (sv[tid + st] == sv[tid] && si[tid + st] < si[tid])) {
                sv[tid] = sv[tid + st]; si[tid] = si[tid + st];
            }
        }
        __syncthreads();
    }
    int idx = si[0];
    float cv = cb[(size_t)idx * 256 + tid];
    float diff = g_ze[b * 256 + tid] - cv;
    g_zq[b * 256 + tid] = cv;
    __shared__ double sl[256];
    sl[tid] = (double)diff * diff;
    __syncthreads();
    for (int st = 128; st > 0; st >>= 1) {
        if (tid < st) sl[tid] += sl[tid + st];
        __syncthreads();
    }
    if (tid == 0) atomicAdd(&g_loss, sl[0]);
}

__global__ void write_loss(float* out, long long pos)
{
    out[pos] = (float)(2.0 * g_loss);
}

// ---------------- host orchestration ----------------
extern "C" void kernel_launch(void* const* d_in, const int* in_sizes, int n_in,
                              void* d_out, int out_size)
{
    const float* x     = (const float*)d_in[0];
    const float* ew1   = (const float*)d_in[1];
    const float* eb1   = (const float*)d_in[2];
    const float* ew2   = (const float*)d_in[3];
    const float* eb2   = (const float*)d_in[4];
    const float* ew3   = (const float*)d_in[5];
    const float* eb3   = (const float*)d_in[6];
    const float* ew4   = (const float*)d_in[7];
    const float* eb4   = (const float*)d_in[8];
    const float* ewmu  = (const float*)d_in[9];
    const float* ebmu  = (const float*)d_in[10];
    const float* ewcov = (const float*)d_in[11];
    const float* ebcov = (const float*)d_in[12];
    const float* cb    = (const float*)d_in[13];
    const float* dwfc  = (const float*)d_in[14];
    const float* dbfc  = (const float*)d_in[15];
    const float* dwt1  = (const float*)d_in[16];
    const float* dbt1  = (const float*)d_in[17];
    const float* dwt2  = (const float*)d_in[18];
    const float* dbt2  = (const float*)d_in[19];
    const float* dwt3  = (const float*)d_in[20];
    const float* dbt3  = (const float*)d_in[21];
    const float* dwt31 = (const float*)d_in[22];
    const float* dbt31 = (const float*)d_in[23];
    const float* dwt4  = (const float*)d_in[24];
    const float* dbt4  = (const float*)d_in[25];
    float* out = (float*)d_out;

    float *A, *Bf, *ze, *zq, *gm, *gr;
    cudaGetSymbolAddress((void**)&A,  g_bufA);
    cudaGetSymbolAddress((void**)&Bf, g_bufB);
    cudaGetSymbolAddress((void**)&ze, g_ze);
    cudaGetSymbolAddress((void**)&zq, g_zq);
    cudaGetSymbolAddress((void**)&gm, g_mean);
    cudaGetSymbolAddress((void**)&gr, g_rstd);

    init_zero<<<1, 256>>>();

    // ---- Encoder (BN stats fused into conv epilogues) ----
    conv3s2<3, 64, 64, 32, 16, 16, 1, 32, 8, 3>
        <<<dim3(1024, 1), 256>>>(x, ew1, eb1, nullptr, nullptr, Bf);
    bn_finalize<<<1, 256>>>(32, 1.f / (256.f * 1024.f));

    conv3s2<32, 32, 32, 64, 16, 16, 1, 64, 16, 4>
        <<<dim3(256, 1), 256>>>(Bf, ew2, eb2, gm, gr, A);
    bn_finalize<<<1, 256>>>(64, 1.f / (256.f * 256.f));

    conv3s2<64, 16, 16, 128, 8, 8, 1, 128, 8, 8>
        <<<dim3(256, 1), 256>>>(A, ew3, eb3, gm, gr, Bf);
    bn_finalize<<<1, 256>>>(128, 1.f / (256.f * 64.f));

    conv3s2<128, 8, 8, 256, 4, 4, 2, 128, 8, 8>
        <<<dim3(128, 2), 128>>>(Bf, ew4, eb4, gm, gr, A);
    bn_finalize<<<1, 256>>>(256, 1.f / (256.f * 16.f));

    // ---- FC heads (split-K, BN4 fused), partials in Bf ----
    gemm_heads_splitk<<<dim3(4, 4, 8), 256>>>(A, ewmu, ewcov, Bf, 512);
    head_combine<<<256, 256>>>(Bf, ebmu, ebcov, 8);

    // ---- VQ ----
    cnorm_k<<<1024, 256>>>(cb);
    gemm64<<<dim3(128, 4), 256>>>(ze, cb, nullptr, Bf, 256, 8192, 256, 8192, 0);
    vq_argmin<<<BATCH, 256>>>(Bf, cb);

    // ---- Decoder FC ----
    gemm64<<<dim3(64, 4), 256>>>(zq, dwfc, dbfc, A, 256, 4096, 256, 4096, 0);

    // ---- Decoder (BN stats fused into convT epilogues) ----
    convt3s2<256, 4, 4, 128, 8, 8, 2, 64, 4, 16>
        <<<dim3(128, 2), 128>>>(A, dwt1, dbt1, nullptr, nullptr, Bf);
    bn_finalize<<<1, 256>>>(128, 1.f / (256.f * 64.f));

    convt3s2<128, 8, 8, 64, 16, 16, 1, 64, 4, 16>
        <<<dim3(256, 1), 256>>>(Bf, dwt2, dbt2, gm, gr, A);
    bn_finalize<<<1, 256>>>(64, 1.f / (256.f * 256.f));

    convt3s2<64, 16, 16, 32, 32, 32, 1, 32, 4, 16>
        <<<dim3(256, 1), 512>>>(A, dwt3, dbt3, gm, gr, Bf);
    bn_finalize<<<1, 256>>>(32, 1.f / (256.f * 1024.f));

    convt3s2<32, 32, 32, 32, 32, 32, 1, 32, 4, 16>
        <<<dim3(1024, 1), 512>>>(Bf, dwt31, dbt31, gm, gr, A);
    bn_finalize<<<1, 256>>>(32, 1.f / (256.f * 4096.f));

    convt4_s1_tanh<<<dim3(1024, 1), 128>>>(A, dwt4, dbt4, gm, gr, out);

    // ---- scalar vq_loss ----
    write_loss<<<1, 1>>>(out, (long long)out_size - 1);
}